// round 13
// baseline (speedup 1.0000x reference)
#include <cuda_runtime.h>
#include <cuda_fp16.h>
#include <cstdint>

// UnionLayer via Taylor expansion -> fp8 e4m3 tensor-core GEMM (mma.sync m16n8k32).
//   -log(1-t) = sum_{n=1..6} t^n / n,  t = u*w in [0, 0.5)
//   con: u = 1-x, y = 1/(1+S);  dis: u = x, y = 1 - 1/(1+S)
// R13: all powers PRECOMPUTED to e4m3 scratch by a prep kernel; the GEMM
// mainloop is pure LDG.128 + mma.sync.m16n8k32.e4m3 (no chains, no cvt, no smem).
// Rationale: measured invariant rt ~18.5 cyc per mma.sync instr per SMSP across
// all schedules -> halve instruction count via K=32 fp8 MMAs.
// Scratch layout (16B granule per (row, n, u2, t4)):
//   bytes 0-3  : unit 2*u2,   k = 4*t4+0..3      (klo)
//   bytes 4-7  : unit 2*u2,   k = 16+4*t4+0..3   (khi)
//   bytes 8-15 : unit 2*u2+1, same klo/khi
// -> one LDG.128 = A (a0,a2) or B (b0,b1) fragments for TWO k32 units.
// GEMM: grid (8,8,2), 256 thr, warp = 16m x 32n tile, 48 iters (8 u2 x 6 n).

#define DDIM    512
#define NOUT    512
#define NCOLS   256
#define NTERMS  6
#define MTILE   128
#define NTILE   32
#define THREADS 256

__device__ uint8_t AS[2][1024 * NTERMS * DDIM];   // u^(n+1)        (6 MB)
__device__ uint8_t BS[2][NCOLS * NTERMS * DDIM];  // w^(n+1)/(n+1)  (1.5 MB)

__device__ __forceinline__ uint16_t cvt2_e4m3(float hi, float lo) {
    uint16_t r;
    asm("cvt.rn.satfinite.e4m3x2.f32 %0, %1, %2;" : "=h"(r) : "f"(hi), "f"(lo));
    return r;
}

// ---- prep: compute powers in fp32, round once to e4m3, store in granules ----
__global__ __launch_bounds__(256) void prep_kernel(
    const float* __restrict__ x,
    const float* __restrict__ Wcon,
    const float* __restrict__ Wdis)
{
    const int t = blockIdx.x * blockDim.x + threadIdx.x;
    const float inv_n[NTERMS] = {1.f, 0.5f, 1.f/3.f, 0.25f, 0.2f, 1.f/6.f};

    if (t < 131072) {
        // A: z = t>>16, row = (t>>6)&1023, u = (t>>2)&15, t4 = t&3
        const int z  = t >> 16;
        const int r  = (t >> 6) & 1023;
        const int u  = (t >> 2) & 15;
        const int t4 = t & 3;
        const int d0 = u * 32 + t4 * 4;
        float4 v0 = *reinterpret_cast<const float4*>(&x[r * DDIM + d0]);
        float4 v1 = *reinterpret_cast<const float4*>(&x[r * DDIM + d0 + 16]);
        float base[8], cur[8];
        base[0]=v0.x; base[1]=v0.y; base[2]=v0.z; base[3]=v0.w;
        base[4]=v1.x; base[5]=v1.y; base[6]=v1.z; base[7]=v1.w;
        if (z == 0) {
#pragma unroll
            for (int i = 0; i < 8; i++) base[i] = 1.0f - base[i];
        }
#pragma unroll
        for (int i = 0; i < 8; i++) cur[i] = base[i];
        uint8_t* g = &AS[z][(r * NTERMS) * DDIM + (u >> 1) * 64 + t4 * 16 + (u & 1) * 8];
#pragma unroll
        for (int n = 0; n < NTERMS; n++) {
            if (n) {
#pragma unroll
                for (int i = 0; i < 8; i++) cur[i] *= base[i];
            }
            uint32_t w0 = (uint32_t)cvt2_e4m3(cur[1], cur[0])
                        | ((uint32_t)cvt2_e4m3(cur[3], cur[2]) << 16);
            uint32_t w1 = (uint32_t)cvt2_e4m3(cur[5], cur[4])
                        | ((uint32_t)cvt2_e4m3(cur[7], cur[6]) << 16);
            *reinterpret_cast<uint2*>(g + n * DDIM) = make_uint2(w0, w1);
        }
    } else if (t < 131072 + 32768) {
        const int i  = t - 131072;
        const int z  = i >> 14;
        const int c  = (i >> 6) & 255;
        const int u  = (i >> 2) & 15;
        const int t4 = i & 3;
        const int d0 = u * 32 + t4 * 4;
        const float* src = z ? Wdis : Wcon;
        float4 v0 = *reinterpret_cast<const float4*>(&src[c * DDIM + d0]);
        float4 v1 = *reinterpret_cast<const float4*>(&src[c * DDIM + d0 + 16]);
        float base[8], pw[8];
        base[0]=v0.x; base[1]=v0.y; base[2]=v0.z; base[3]=v0.w;
        base[4]=v1.x; base[5]=v1.y; base[6]=v1.z; base[7]=v1.w;
#pragma unroll
        for (int k = 0; k < 8; k++) pw[k] = base[k];
        uint8_t* g = &BS[z][(c * NTERMS) * DDIM + (u >> 1) * 64 + t4 * 16 + (u & 1) * 8];
#pragma unroll
        for (int n = 0; n < NTERMS; n++) {
            if (n) {
#pragma unroll
                for (int k = 0; k < 8; k++) pw[k] *= base[k];
            }
            float val[8];
#pragma unroll
            for (int k = 0; k < 8; k++) val[k] = pw[k] * inv_n[n];
            uint32_t w0 = (uint32_t)cvt2_e4m3(val[1], val[0])
                        | ((uint32_t)cvt2_e4m3(val[3], val[2]) << 16);
            uint32_t w1 = (uint32_t)cvt2_e4m3(val[5], val[4])
                        | ((uint32_t)cvt2_e4m3(val[7], val[6]) << 16);
            *reinterpret_cast<uint2*>(g + n * DDIM) = make_uint2(w0, w1);
        }
    }
}

__device__ __forceinline__ void mma_e4m3(float* c, uint32_t a0, uint32_t a1,
                                         uint32_t a2, uint32_t a3,
                                         uint32_t b0, uint32_t b1) {
    asm volatile(
        "mma.sync.aligned.m16n8k32.row.col.f32.e4m3.e4m3.f32 "
        "{%0,%1,%2,%3}, {%4,%5,%6,%7}, {%8,%9}, {%0,%1,%2,%3};"
        : "+f"(c[0]), "+f"(c[1]), "+f"(c[2]), "+f"(c[3])
        : "r"(a0), "r"(a1), "r"(a2), "r"(a3), "r"(b0), "r"(b1));
}

// ---- GEMM: warp = 16m x 32n, pure load+mma ----
__global__ __launch_bounds__(THREADS) void union_fp8_kernel(
    float* __restrict__ out)
{
    const int tid  = threadIdx.x;
    const int wid  = tid >> 5;         // 0..7 -> 16-row slice
    const int lane = tid & 31;
    const int g    = lane >> 2;        // 0..7
    const int t4   = lane & 3;         // 0..3
    const int bn0  = blockIdx.x * NTILE;
    const int bm0  = blockIdx.y * MTILE;
    const int z    = blockIdx.z;       // 0 = con, 1 = dis

    const uint8_t* __restrict__ aP0 =
        &AS[z][((bm0 + wid * 16 + g)     * NTERMS) * DDIM + t4 * 16];
    const uint8_t* __restrict__ aP1 =
        &AS[z][((bm0 + wid * 16 + g + 8) * NTERMS) * DDIM + t4 * 16];
    const uint8_t* __restrict__ bP0 = &BS[z][((bn0 +  0 + g) * NTERMS) * DDIM + t4 * 16];
    const uint8_t* __restrict__ bP1 = &BS[z][((bn0 +  8 + g) * NTERMS) * DDIM + t4 * 16];
    const uint8_t* __restrict__ bP2 = &BS[z][((bn0 + 16 + g) * NTERMS) * DDIM + t4 * 16];
    const uint8_t* __restrict__ bP3 = &BS[z][((bn0 + 24 + g) * NTERMS) * DDIM + t4 * 16];

    float acc[4][4];
#pragma unroll
    for (int j = 0; j < 4; j++)
#pragma unroll
        for (int c = 0; c < 4; c++) acc[j][c] = 0.0f;

    // iteration order: it = u2*6 + n;  offset = n*512 + u2*64
    uint4 st[2][6];
    {
        st[0][0] = *reinterpret_cast<const uint4*>(aP0);
        st[0][1] = *reinterpret_cast<const uint4*>(aP1);
        st[0][2] = *reinterpret_cast<const uint4*>(bP0);
        st[0][3] = *reinterpret_cast<const uint4*>(bP1);
        st[0][4] = *reinterpret_cast<const uint4*>(bP2);
        st[0][5] = *reinterpret_cast<const uint4*>(bP3);
    }

#pragma unroll 6
    for (int it = 0; it < 48; it++) {
        const int b = it & 1;
        if (it + 1 < 48) {
            const int nit = it + 1;
            const int off = (nit % 6) * 512 + (nit / 6) * 64;
            st[b ^ 1][0] = *reinterpret_cast<const uint4*>(aP0 + off);
            st[b ^ 1][1] = *reinterpret_cast<const uint4*>(aP1 + off);
            st[b ^ 1][2] = *reinterpret_cast<const uint4*>(bP0 + off);
            st[b ^ 1][3] = *reinterpret_cast<const uint4*>(bP1 + off);
            st[b ^ 1][4] = *reinterpret_cast<const uint4*>(bP2 + off);
            st[b ^ 1][5] = *reinterpret_cast<const uint4*>(bP3 + off);
        }
        // unit 0 (fields .x/.y), unit 1 (fields .z/.w)
        mma_e4m3(acc[0], st[b][0].x, st[b][1].x, st[b][0].y, st[b][1].y, st[b][2].x, st[b][2].y);
        mma_e4m3(acc[1], st[b][0].x, st[b][1].x, st[b][0].y, st[b][1].y, st[b][3].x, st[b][3].y);
        mma_e4m3(acc[2], st[b][0].x, st[b][1].x, st[b][0].y, st[b][1].y, st[b][4].x, st[b][4].y);
        mma_e4m3(acc[3], st[b][0].x, st[b][1].x, st[b][0].y, st[b][1].y, st[b][5].x, st[b][5].y);
        mma_e4m3(acc[0], st[b][0].z, st[b][1].z, st[b][0].w, st[b][1].w, st[b][2].z, st[b][2].w);
        mma_e4m3(acc[1], st[b][0].z, st[b][1].z, st[b][0].w, st[b][1].w, st[b][3].z, st[b][3].w);
        mma_e4m3(acc[2], st[b][0].z, st[b][1].z, st[b][0].w, st[b][1].w, st[b][4].z, st[b][4].w);
        mma_e4m3(acc[3], st[b][0].z, st[b][1].z, st[b][0].w, st[b][1].w, st[b][5].z, st[b][5].w);
    }

    // ---- epilogue: y = 1/(1+S); dis: 1 - y ----
#pragma unroll
    for (int half = 0; half < 2; half++) {       // c0c1: row g; c2c3: row g+8
        const int m = bm0 + wid * 16 + g + half * 8;
#pragma unroll
        for (int j = 0; j < 4; j++) {
            float S0 = acc[j][half * 2 + 0];
            float S1 = acc[j][half * 2 + 1];
            float y0 = 1.0f / (1.0f + S0);
            float y1 = 1.0f / (1.0f + S1);
            if (z) { y0 = 1.0f - y0; y1 = 1.0f - y1; }
            const int col = bn0 + j * 8 + 2 * t4;
            *reinterpret_cast<float2*>(&out[m * NOUT + z * NCOLS + col]) =
                make_float2(y0, y1);
        }
    }
}

extern "C" void kernel_launch(void* const* d_in, const int* in_sizes, int n_in,
                              void* d_out, int out_size)
{
    const float* x    = (const float*)d_in[0];
    const float* Wcon = (const float*)d_in[1];
    const float* Wdis = (const float*)d_in[2];
    float* out = (float*)d_out;

    prep_kernel<<<640, 256>>>(x, Wcon, Wdis);    // 163840 threads

    dim3 grid(NCOLS / NTILE, 1024 / MTILE, 2);   // (8, 8, 2) = 128 CTAs
    union_fp8_kernel<<<grid, THREADS>>>(out);
}

// round 14
// speedup vs baseline: 1.6122x; 1.6122x over previous
#include <cuda_runtime.h>
#include <cuda_fp16.h>
#include <cstdint>

// UnionLayer via degree-5 CHEBYSHEV/minimax polynomial -> fp16 mma.sync GEMM.
//   -log(1-t) ~= c0 + c1 t + c2 t^2 + c3 t^3 + c4 t^4 + c5 t^5  on t in [0, 0.5]
//   (Chebyshev truncation of ln: abs err ~8.5e-6, vs Taylor needing 7-8 terms)
//   c0 = -7.51e-6, c1 = 1.0010196, c2 = 0.47765325, c3 = 0.50749266,
//   c4 = -0.33063743, c5 = 0.97439233
//   S[b,nh] = sum_d P(t_d) = 512*c0 + sum_n c_n * (u^n . w^n)  == GEMM, K = 5*512
//   con: u = 1-x, y = 1/(1+S);  dis: u = x, y = 1 - 1/(1+S)
// R14 = R10 mainloop (term-level software-pipelined register fragments, 256 thr,
// 8 warps: 4 m-slices x 2 d-halves) with NTERMS 7 -> 5:
//   B chain uses ratio factors r_n = c_{n+1}/c_n; c1 and 512*c0 fold into the
//   epilogue FMA (S = c1*acc + 512*c0). MMA count -28.6%.
// Measured invariant: one m16n8k16 per ~19cyc/SMSP regardless of schedule ->
// time ~ MMA instruction count. Grid (8, 8, 2) = 128 CTAs.

#define DDIM    512
#define NOUT    512
#define NCOLS   256
#define NTERMS  5
#define MTILE   128
#define NTILE   32
#define THREADS 256

// chain ratios r_n = c_{n+1}/c_n (kf[0] unused)
#define R1  0.4771667f
#define R2  1.0624706f
#define R3 -0.6515116f
#define R4 -2.9469168f
// epilogue: S = C1E * acc + C0E
#define C1E 1.0010196f
#define C0E -0.0038451f    // 512 * c0

__device__ __forceinline__ void mma16816(float* c, uint32_t a0, uint32_t a1,
                                         uint32_t a2, uint32_t a3,
                                         uint32_t b0, uint32_t b1) {
    asm volatile(
        "mma.sync.aligned.m16n8k16.row.col.f32.f16.f16.f32 "
        "{%0,%1,%2,%3}, {%4,%5,%6,%7}, {%8,%9}, {%0,%1,%2,%3};"
        : "+f"(c[0]), "+f"(c[1]), "+f"(c[2]), "+f"(c[3])
        : "r"(a0), "r"(a1), "r"(a2), "r"(a3), "r"(b0), "r"(b1));
}

__device__ __forceinline__ uint32_t h2u(__half2 h) {
    return *reinterpret_cast<uint32_t*>(&h);
}

__global__ __launch_bounds__(THREADS) void union_mma_kernel(
    const float* __restrict__ x,
    const float* __restrict__ Wcon,
    const float* __restrict__ Wdis,
    float* __restrict__ out)
{
    __shared__ float red[4][32][32];   // d-half-1 partials (16 KB)

    const int tid  = threadIdx.x;
    const int wid  = tid >> 5;
    const int lane = tid & 31;
    const int g    = lane >> 2;        // 0..7
    const int t4   = lane & 3;         // 0..3
    const int msl  = wid & 3;          // m-slice (32 rows)
    const int dh   = wid >> 2;         // d-half 0/1
    const int bn0  = blockIdx.x * NTILE;
    const int bm0  = blockIdx.y * MTILE;
    const int z    = blockIdx.z;       // 0 = con, 1 = dis
    const float* __restrict__ W = z ? Wdis : Wcon;

    const float* __restrict__ pA = &x[(bm0 + msl * 32 + g) * DDIM + dh * 256 + 2 * t4];
    const float* __restrict__ pB = &W[(bn0 + g) * DDIM + dh * 256 + 2 * t4];

    float acc[2][4][4];
#pragma unroll
    for (int mt = 0; mt < 2; mt++)
#pragma unroll
        for (int nt = 0; nt < 4; nt++)
#pragma unroll
            for (int c = 0; c < 4; c++) acc[mt][nt][c] = 0.0f;

    const float kf[NTERMS] = {0.f, R1, R2, R3, R4};
    const int stag = msl * 4;          // per-warp unit-order stagger

    // staged raw for one 16-d unit: [row][pair]  (pair p -> d offset p*8 + {0,1})
    float2 sA[4][2], sB[4][2];
    {
        int off = ((0 + stag) & 15) * 16;
#pragma unroll
        for (int r = 0; r < 4; r++)
#pragma unroll
            for (int p = 0; p < 2; p++) {
                sA[r][p] = *reinterpret_cast<const float2*>(pA + r * 8 * DDIM + off + p * 8);
                sB[r][p] = *reinterpret_cast<const float2*>(pB + r * 8 * DDIM + off + p * 8);
            }
    }

#pragma unroll 1
    for (int u = 0; u < 16; u++) {
        // ---- build bases + term-1 fragments (buffer 0) ----
        __half2 baseA[4][2], baseB[4][2], curA[2][4][2], curB[2][4][2];
#pragma unroll
        for (int r = 0; r < 4; r++)
#pragma unroll
            for (int p = 0; p < 2; p++) {
                float ux = sA[r][p].x, uy = sA[r][p].y;
                if (z == 0) { ux = 1.0f - ux; uy = 1.0f - uy; }
                baseA[r][p]   = __floats2half2_rn(ux, uy);
                baseB[r][p]   = __floats2half2_rn(sB[r][p].x, sB[r][p].y);
                curA[0][r][p] = baseA[r][p];
                curB[0][r][p] = baseB[r][p];
            }

        // ---- prefetch next unit's raw (consumed next iteration) ----
        if (u + 1 < 16) {
            int off = ((u + 1 + stag) & 15) * 16;
#pragma unroll
            for (int r = 0; r < 4; r++)
#pragma unroll
                for (int p = 0; p < 2; p++) {
                    sA[r][p] = *reinterpret_cast<const float2*>(pA + r * 8 * DDIM + off + p * 8);
                    sB[r][p] = *reinterpret_cast<const float2*>(pB + r * 8 * DDIM + off + p * 8);
                }
        }

        // ---- 5 poly terms, software-pipelined: chain(n+1) BEFORE mma(n) ----
#pragma unroll
        for (int n = 0; n < NTERMS; n++) {
            const int cb = n & 1, nb = (n + 1) & 1;
            if (n + 1 < NTERMS) {
                const __half2 kfh = __float2half2_rn(kf[n + 1]);
#pragma unroll
                for (int r = 0; r < 4; r++)
#pragma unroll
                    for (int p = 0; p < 2; p++) {
                        curA[nb][r][p] = __hmul2(curA[cb][r][p], baseA[r][p]);
                        __half2 bb     = __hmul2(baseB[r][p], kfh);     // independent
                        curB[nb][r][p] = __hmul2(curB[cb][r][p], bb);   // 1 dependent link
                    }
            }
#pragma unroll
            for (int mt = 0; mt < 2; mt++) {
                uint32_t a0 = h2u(curA[cb][mt * 2 + 0][0]);
                uint32_t a1 = h2u(curA[cb][mt * 2 + 1][0]);
                uint32_t a2 = h2u(curA[cb][mt * 2 + 0][1]);
                uint32_t a3 = h2u(curA[cb][mt * 2 + 1][1]);
#pragma unroll
                for (int nt = 0; nt < 4; nt++) {
                    mma16816(acc[mt][nt], a0, a1, a2, a3,
                             h2u(curB[cb][nt][0]), h2u(curB[cb][nt][1]));
                }
            }
        }
    }

    // ---- merge d-halves: half 1 stores, half 0 adds + epilogue ----
    if (dh == 1) {
#pragma unroll
        for (int mt = 0; mt < 2; mt++)
#pragma unroll
            for (int hh = 0; hh < 2; hh++) {
                int r = mt * 16 + hh * 8 + g;
#pragma unroll
                for (int nt = 0; nt < 4; nt++) {
                    *reinterpret_cast<float2*>(&red[msl][r][nt * 8 + 2 * t4]) =
                        make_float2(acc[mt][nt][hh * 2 + 0], acc[mt][nt][hh * 2 + 1]);
                }
            }
    }
    __syncthreads();

    if (dh == 0) {
#pragma unroll
        for (int mt = 0; mt < 2; mt++) {
#pragma unroll
            for (int hh = 0; hh < 2; hh++) {
                int r = mt * 16 + hh * 8 + g;
                int m = bm0 + msl * 32 + r;
#pragma unroll
                for (int nt = 0; nt < 4; nt++) {
                    float2 o = *reinterpret_cast<const float2*>(&red[msl][r][nt * 8 + 2 * t4]);
                    float S0 = fmaf(C1E, acc[mt][nt][hh * 2 + 0] + o.x, C0E);
                    float S1 = fmaf(C1E, acc[mt][nt][hh * 2 + 1] + o.y, C0E);
                    float y0 = 1.0f / (1.0f + S0);
                    float y1 = 1.0f / (1.0f + S1);
                    if (z) { y0 = 1.0f - y0; y1 = 1.0f - y1; }
                    int col = bn0 + nt * 8 + 2 * t4;
                    *reinterpret_cast<float2*>(&out[m * NOUT + z * NCOLS + col]) =
                        make_float2(y0, y1);
                }
            }
        }
    }
}

extern "C" void kernel_launch(void* const* d_in, const int* in_sizes, int n_in,
                              void* d_out, int out_size)
{
    const float* x    = (const float*)d_in[0];
    const float* Wcon = (const float*)d_in[1];
    const float* Wdis = (const float*)d_in[2];
    float* out = (float*)d_out;

    dim3 grid(NCOLS / NTILE, 1024 / MTILE, 2);   // (8, 8, 2) = 128 CTAs
    union_mma_kernel<<<grid, THREADS>>>(x, Wcon, Wdis, out);
}